// round 5
// baseline (speedup 1.0000x reference)
#include <cuda_runtime.h>
#include <cuda_bf16.h>
#include <math.h>

#define NEGV (-1e30f)

constexpr int C       = 256;
constexpr int LMAX    = 128;
constexpr int THREADS = 512;   // 16 warps
constexpr int MAXB    = 64;
constexpr int MPITCH  = 84;    // uints per Ms row (336B)
constexpr int MCHUNK  = 20;    // uint offset per h-chunk
constexpr int PPITCH  = 260;   // floats per p copy (h-read stride 324 -> conflict-free)
constexpr int XSTG    = 8;     // x ring stages
constexpr int PDIST   = 6;     // prefetch distance (wait_group 4 => stages k, k+1 ready)

__device__ float g_f  [MAXB][C];
__device__ float g_g  [MAXB][C];
__device__ float g_a  [MAXB][LMAX];
__device__ float g_bt [MAXB][LMAX];
__device__ float g_lsf[MAXB];
__device__ float g_lsg[MAXB];

struct SmemLayout {
  unsigned int Ms[C * MPITCH];     // bf16x2-packed half of M: 86016 B
  float pbuf[2][4 * PPITCH];       // double-buffered, 4 bank-shifted copies
  float xring[XSTG][C];            // deep-prefetched x_t ring (8 KB)
  float nb[2][LMAX + 2];           // numerator DP
  float red[16];
  int   labs[LMAX];
};

#define FMA2(acc,a,b)     asm("fma.rn.f32x2 %0, %1, %2, %0;" : "+l"(acc) : "l"(a), "l"(b))
#define PACKF2(d,lo,hi)   asm("mov.b64 %0, {%1, %2};" : "=l"(d) : "f"(lo), "f"(hi))
#define UNPACKF2(lo,hi,v) asm("mov.b64 {%0, %1}, %2;" : "=f"(lo), "=f"(hi) : "l"(v))
#define CP_ASYNC4(smem_u32, gptr) \
  asm volatile("cp.async.ca.shared.global [%0], [%1], 4;" :: "r"(smem_u32), "l"(gptr))
#define CP_COMMIT()  asm volatile("cp.async.commit_group;")
#define CP_WAIT4()   asm volatile("cp.async.wait_group 4;")

__device__ __forceinline__ float lse2(float a, float b) {
  float mx = fmaxf(a, b);
  float mn = fminf(a, b);
  return mx + log1pf(__expf(mn - mx));
}

__global__ void __launch_bounds__(THREADS, 1)
chain_kernel(const float* __restrict__ x, const float* __restrict__ trans,
             const int* __restrict__ labels, const int* __restrict__ durations,
             int T, int L)
{
  extern __shared__ char smraw[];
  SmemLayout& sm = *reinterpret_cast<SmemLayout*>(smraw);

  const int  tid  = threadIdx.x;
  const int  lane = tid & 31;
  const int  w    = tid >> 5;
  const int  b    = blockIdx.x >> 1;
  const bool bwd  = blockIdx.x & 1;

  const int jp = w * 8 + (lane >> 2);   // j-pair 0..127
  const int h  = lane & 3;              // c-quarter
  const int j0 = 2 * jp, j1 = j0 + 1;
  const int cbase = h * 64;

  const int D      = durations[b];
  const int m      = D >> 1;
  const int nsteps = bwd ? (D - 1 - m) : m;
  const int dt     = bwd ? -1 : 1;
  const int t0     = bwd ? (D - 1) : 1;   // ring stage k holds x[t0 + dt*k]

  // ---- register half of M (fp32, c-paired f32x2)
  unsigned long long MrA[16], MrB[16];
  #pragma unroll
  for (int k = 0; k < 16; ++k) {
    int c0 = cbase + 2 * k, c1 = c0 + 1;
    float a0, a1, b0, b1;
    if (!bwd) {
      a0 = __expf(trans[c0 * C + j0]); a1 = __expf(trans[c1 * C + j0]);
      b0 = __expf(trans[c0 * C + j1]); b1 = __expf(trans[c1 * C + j1]);
    } else {
      a0 = __expf(trans[j0 * C + c0]); a1 = __expf(trans[j0 * C + c1]);
      b0 = __expf(trans[j1 * C + c0]); b1 = __expf(trans[j1 * C + c1]);
    }
    PACKF2(MrA[k], a0, a1);
    PACKF2(MrB[k], b0, b1);
  }

  // ---- SMEM half of M (bf16x2; hi uses raw-f32 expand w/ bias correction)
  #pragma unroll
  for (int i = 0; i < 16; ++i) {
    int c0 = cbase + 32 + 2 * i, c1 = c0 + 1;
    #pragma unroll
    for (int jj = 0; jj < 2; ++jj) {
      int j = j0 + jj;
      float v0, v1;
      if (!bwd) { v0 = __expf(trans[c0 * C + j]); v1 = __expf(trans[c1 * C + j]); }
      else      { v0 = __expf(trans[j * C + c0]); v1 = __expf(trans[j * C + c1]); }
      v1 *= 0.9986f;
      unsigned int lo = (unsigned int)__bfloat16_as_ushort(__float2bfloat16(v0));
      unsigned int hi = (unsigned int)__bfloat16_as_ushort(__float2bfloat16(v1));
      sm.Ms[j * MPITCH + MCHUNK * h + i] = (hi << 16) | lo;
    }
  }
  for (int l = tid; l < L; l += THREADS) sm.labs[l] = labels[b * L + l];

  const float* xb = x + (size_t)b * T * C;
  const unsigned int xr0 = (unsigned int)__cvta_generic_to_shared(&sm.xring[0][0]);

  // ---- prologue: prefetch ring stages 0..PDIST-1
  for (int s = 0; s < PDIST; ++s) {
    if (tid < C) {
      int tp = t0 + dt * s;
      tp = max(0, min(tp, T - 1));
      CP_ASYNC4(xr0 + (unsigned)((s * C + tid) * 4), xb + (size_t)tp * C + tid);
    }
    CP_COMMIT();
  }

  // ---- init p (4 copies), red, nb
  if (tid < C) {
    int tp = bwd ? (D - 1) : 0;
    float w0 = __expf(xb[(size_t)tp * C + tid]);   // one-time LDG
    #pragma unroll
    for (int cp = 0; cp < 4; ++cp) sm.pbuf[0][cp * PPITCH + tid] = w0;
    float rv = w0;
    #pragma unroll
    for (int o = 16; o; o >>= 1) rv += __shfl_xor_sync(0xffffffffu, rv, o);
    if (lane == 0) sm.red[w] = rv;
  } else if (lane == 0) {
    sm.red[w] = 0.0f;
  }
  if (tid < LMAX + 2) { sm.nb[0][tid] = NEGV; sm.nb[1][tid] = NEGV; }
  __syncthreads();
  if (tid == 0) {
    if (!bwd) sm.nb[0][1] = xb[sm.labs[0]];
    else      sm.nb[0][L] = 0.0f;
  }

  float logS = 0.0f;
  int   cur  = 0;

  const unsigned int* MsJ0 = sm.Ms + j0 * MPITCH + MCHUNK * h;
  const unsigned int* MsJ1 = sm.Ms + j1 * MPITCH + MCHUNK * h;

  const bool isnum = (h == 1);
  const int  lnum  = jp;

  for (int k = 0; k < nsteps; ++k) {
    CP_WAIT4();        // stages k and k+1 complete (for issuing threads)
    __syncthreads();   // single barrier: ring stages, pbuf[cur], nb[cur], red visible
    const bool more  = (k + 1) < nsteps;
    const bool use_S = (k & 3) == 0;
    const bool wrred = (((k + 1) & 3) == 0) || !more;
    const int  sk    = k & (XSTG - 1);
    const int  sk1   = (k + 1) & (XSTG - 1);

    // issue prefetch for stage k+PDIST (clamped; harmless overfetch)
    if (tid < C) {
      int tp = t0 + dt * (k + PDIST);
      tp = max(0, min(tp, T - 1));
      int ss = (k + PDIST) & (XSTG - 1);
      CP_ASYNC4(xr0 + (unsigned)((ss * C + tid) * 4), xb + (size_t)tp * C + tid);
    }
    CP_COMMIT();

    const float* pr = sm.pbuf[cur] + 324 * h;

    unsigned long long acc0 = 0ull, acc1 = 0ull;
    // register half
    #pragma unroll
    for (int q = 0; q < 8; ++q) {
      ulonglong2 pv = *reinterpret_cast<const ulonglong2*>(pr + 4 * q);
      FMA2(acc0, pv.x, MrA[2 * q]);  FMA2(acc0, pv.y, MrA[2 * q + 1]);
      FMA2(acc1, pv.x, MrB[2 * q]);  FMA2(acc1, pv.y, MrB[2 * q + 1]);
    }
    // smem bf16 half
    #pragma unroll
    for (int q = 0; q < 4; ++q) {
      uint4 m0 = *reinterpret_cast<const uint4*>(MsJ0 + 4 * q);
      uint4 m1 = *reinterpret_cast<const uint4*>(MsJ1 + 4 * q);
      ulonglong2 pa = *reinterpret_cast<const ulonglong2*>(pr + 32 + 8 * q);
      ulonglong2 pb = *reinterpret_cast<const ulonglong2*>(pr + 32 + 8 * q + 4);
      unsigned long long e;
      PACKF2(e, __uint_as_float(m0.x << 16), __uint_as_float(m0.x)); FMA2(acc0, pa.x, e);
      PACKF2(e, __uint_as_float(m0.y << 16), __uint_as_float(m0.y)); FMA2(acc0, pa.y, e);
      PACKF2(e, __uint_as_float(m0.z << 16), __uint_as_float(m0.z)); FMA2(acc0, pb.x, e);
      PACKF2(e, __uint_as_float(m0.w << 16), __uint_as_float(m0.w)); FMA2(acc0, pb.y, e);
      PACKF2(e, __uint_as_float(m1.x << 16), __uint_as_float(m1.x)); FMA2(acc1, pa.x, e);
      PACKF2(e, __uint_as_float(m1.y << 16), __uint_as_float(m1.y)); FMA2(acc1, pa.y, e);
      PACKF2(e, __uint_as_float(m1.z << 16), __uint_as_float(m1.z)); FMA2(acc1, pb.x, e);
      PACKF2(e, __uint_as_float(m1.w << 16), __uint_as_float(m1.w)); FMA2(acc1, pb.y, e);
    }

    float y0l, y0h, y1l, y1h;
    UNPACKF2(y0l, y0h, acc0);
    UNPACKF2(y1l, y1h, acc1);
    float y0 = y0l + y0h;
    float y1 = y1l + y1h;
    y0 += __shfl_xor_sync(0xffffffffu, y0, 1);
    y0 += __shfl_xor_sync(0xffffffffu, y0, 2);
    y1 += __shfl_xor_sync(0xffffffffu, y1, 1);
    y1 += __shfl_xor_sync(0xffffffffu, y1, 2);

    float rs = 1.0f;
    if (use_S) {
      float sp = sm.red[lane & 15];
      #pragma unroll
      for (int o = 8; o; o >>= 1) sp += __shfl_xor_sync(0xffffffffu, sp, o);
      rs = 1.0f / sp;
      if (tid == 0) logS += logf(sp);
    }

    float wn0, wn1;
    if (!bwd) {
      float2 xc = *reinterpret_cast<const float2*>(&sm.xring[sk][j0]);
      wn0 = y0 * __expf(xc.x) * rs;
      wn1 = y1 * __expf(xc.y) * rs;
    } else {
      wn0 = y0 * rs;
      wn1 = y1 * rs;
      if (more) {
        float2 xn = *reinterpret_cast<const float2*>(&sm.xring[sk1][j0]);
        wn0 *= __expf(xn.x);
        wn1 *= __expf(xn.y);
      }
    }
    *reinterpret_cast<float2*>(&sm.pbuf[cur ^ 1][h * PPITCH + j0]) = make_float2(wn0, wn1);

    if (wrred) {
      float rv = (h == 0) ? (wn0 + wn1) : 0.0f;
      #pragma unroll
      for (int o = 16; o; o >>= 1) rv += __shfl_xor_sync(0xffffffffu, rv, o);
      if (lane == 0) sm.red[w] = rv;
    }

    if (isnum && lnum < L) {
      int l = lnum;
      float nnew;
      if (!bwd) {
        float e = sm.xring[sk][sm.labs[l]];
        nnew = lse2(sm.nb[cur][l + 1], sm.nb[cur][l]) + e;
      } else {
        float v0 = sm.nb[cur][l + 1] + sm.xring[sk][sm.labs[l]];
        float v1 = NEGV;
        if (l + 1 < L) v1 = sm.nb[cur][l + 2] + sm.xring[sk][sm.labs[l + 1]];
        nnew = lse2(v0, v1);
      }
      sm.nb[cur ^ 1][l + 1] = nnew;
    }

    cur ^= 1;
  }
  __syncthreads();

  float sp = sm.red[lane & 15];
  #pragma unroll
  for (int o = 8; o; o >>= 1) sp += __shfl_xor_sync(0xffffffffu, sp, o);
  const float Sf = sp;

  if (!bwd) {
    if (tid < C)  g_f[b][tid] = sm.pbuf[cur][tid] / Sf;
    if (tid < L)  g_a[b][tid] = sm.nb[cur][tid + 1];
    if (tid == 0) g_lsf[b] = logS + logf(Sf);
  } else {
    if (tid < C)  g_g[b][tid] = sm.pbuf[cur][tid] / Sf;
    if (tid < L)  g_bt[b][tid] = sm.nb[cur][tid + 1];
    if (tid == 0) g_lsg[b] = logS + logf(Sf);
  }
}

__global__ void __launch_bounds__(1024, 1)
combine_kernel(const int* __restrict__ durations, int B, int L,
               float* __restrict__ out, int out_size)
{
  __shared__ float sc[MAXB];
  const int lane = threadIdx.x & 31;
  const int w    = threadIdx.x >> 5;

  for (int b = w; b < B; b += 32) {
    float dot = 0.0f;
    for (int c = lane; c < C; c += 32) dot += g_f[b][c] * g_g[b][c];
    #pragma unroll
    for (int o = 16; o; o >>= 1) dot += __shfl_xor_sync(0xffffffffu, dot, o);

    float mx = -INFINITY;
    for (int l = lane; l < L; l += 32) mx = fmaxf(mx, g_a[b][l] + g_bt[b][l]);
    #pragma unroll
    for (int o = 16; o; o >>= 1) mx = fmaxf(mx, __shfl_xor_sync(0xffffffffu, mx, o));

    float s = 0.0f;
    for (int l = lane; l < L; l += 32) s += expf(g_a[b][l] + g_bt[b][l] - mx);
    #pragma unroll
    for (int o = 16; o; o >>= 1) s += __shfl_xor_sync(0xffffffffu, s, o);

    if (lane == 0) {
      float num = mx + logf(s);
      float den = logf(dot) + g_lsf[b] + g_lsg[b];
      sc[b] = num - den;
    }
  }
  __syncthreads();
  if (threadIdx.x == 0) {
    float tot = 0.0f;
    for (int i = 0; i < B; ++i) tot += sc[i];
    long long fr = 0;
    for (int i = 0; i < B; ++i) fr += durations[i];
    out[0] = tot;
    if (out_size > 1) out[1] = (float)fr;
    if (out_size > 2) out[2] = (float)fr;
  }
}

extern "C" void kernel_launch(void* const* d_in, const int* in_sizes, int n_in,
                              void* d_out, int out_size)
{
  const float* x      = (const float*)d_in[0];
  const float* trans  = (const float*)d_in[1];
  const int*   labels = (const int*)d_in[2];
  const int*   dur    = (const int*)d_in[3];

  int B = in_sizes[3];
  int L = in_sizes[2] / B;
  int T = in_sizes[0] / (B * C);

  size_t smem = sizeof(SmemLayout);
  cudaFuncSetAttribute(chain_kernel, cudaFuncAttributeMaxDynamicSharedMemorySize, (int)smem);

  chain_kernel<<<2 * B, THREADS, smem>>>(x, trans, labels, dur, T, L);
  combine_kernel<<<1, 1024>>>(dur, B, L, (float*)d_out, out_size);
}

// round 8
// speedup vs baseline: 1.1275x; 1.1275x over previous
#include <cuda_runtime.h>
#include <cuda_fp16.h>
#include <math.h>

#define NEGV (-1e30f)

constexpr int C        = 256;
constexpr int LMAX     = 128;
constexpr int THREADS  = 512;   // 16 warps
constexpr int MAXB     = 64;
constexpr int MROW     = 264;   // halves per jp row: [j0|j1]x[h0..h3], 132 words ≡ 4 (mod 32)
constexpr int P32PITCH = 260;   // floats per fp32 p copy
constexpr int P16PITCH = 264;   // halves per fp16 p copy
constexpr int GRID_PAD = 148;

__device__ float g_f  [MAXB][C];
__device__ float g_g  [MAXB][C];
__device__ float g_a  [MAXB][LMAX];
__device__ float g_bt [MAXB][LMAX];
__device__ float g_lsf[MAXB];
__device__ float g_lsg[MAXB];

struct SmemLayout {
  __half Msh[128 * MROW];         // fp16 half of M, jp-paired rows: 67584B
  float  p32[2][4 * P32PITCH];    // fp32 p, 4 bank-shifted copies, double-buffered
  __half p16[2][4 * P16PITCH];    // fp16 p, 4 copies, double-buffered
  float  xt[2][C];                // x_t for numerator gather
  float  nb[2][LMAX + 2];         // numerator DP (log domain)
  float  red[16];
  int    labs[LMAX];
};

#define FMA2(acc,a,b)     asm("fma.rn.f32x2 %0, %1, %2, %0;" : "+l"(acc) : "l"(a), "l"(b))
#define PACKF2(d,lo,hi)   asm("mov.b64 %0, {%1, %2};" : "=l"(d) : "f"(lo), "f"(hi))
#define UNPACKF2(lo,hi,v) asm("mov.b64 {%0, %1}, %2;" : "=f"(lo), "=f"(hi) : "l"(v))

__device__ __forceinline__ float lse2_fast(float a, float b) {
  float mx = fmaxf(a, b);
  float mn = fminf(a, b);
  return mx + __logf(1.0f + __expf(mn - mx));
}

__global__ void __launch_bounds__(THREADS, 1)
chain_kernel(const float* __restrict__ x, const float* __restrict__ trans,
             const int* __restrict__ labels, const int* __restrict__ durations,
             int T, int L, int nwork)
{
  if (blockIdx.x >= (unsigned)nwork) return;

  extern __shared__ char smraw[];
  SmemLayout& sm = *reinterpret_cast<SmemLayout*>(smraw);

  const int  tid  = threadIdx.x;
  const int  lane = tid & 31;
  const int  w    = tid >> 5;
  const int  b    = blockIdx.x >> 1;
  const bool bwd  = blockIdx.x & 1;

  const int jp = w * 8 + (lane >> 2);   // j-pair 0..127
  const int h  = lane & 3;              // c-quarter
  const int j0 = 2 * jp, j1 = j0 + 1;
  const int cbase = h * 64;             // reg: [cbase,cbase+32), smem: [cbase+32,cbase+64)

  const int D      = durations[b];
  const int m      = D >> 1;
  const int nsteps = bwd ? (D - 1 - m) : m;
  const int dt     = bwd ? -1 : 1;
  int t            = bwd ? (D - 1) : 1;

  // ---- register half of M: fp32, c-paired f32x2 (MrA: j0, MrB: j1)
  unsigned long long MrA[16], MrB[16];
  #pragma unroll
  for (int k = 0; k < 16; ++k) {
    int c0 = cbase + 2 * k, c1 = c0 + 1;
    float a0, a1, b0, b1;
    if (!bwd) {
      a0 = __expf(trans[c0 * C + j0]); a1 = __expf(trans[c1 * C + j0]);
      b0 = __expf(trans[c0 * C + j1]); b1 = __expf(trans[c1 * C + j1]);
    } else {
      a0 = __expf(trans[j0 * C + c0]); a1 = __expf(trans[j0 * C + c1]);
      b0 = __expf(trans[j1 * C + c0]); b1 = __expf(trans[j1 * C + c1]);
    }
    PACKF2(MrA[k], a0, a1);
    PACKF2(MrB[k], b0, b1);
  }

  // ---- SMEM half of M: fp16, jp-paired rows [j0:h0..h3 | j1:h0..h3]
  for (int idx = tid; idx < 128 * 256; idx += THREADS) {
    int p  = idx >> 8;           // jp
    int i  = idx & 255;          // 0..255 within row
    int jj = i >> 7;             // 0: j0, 1: j1
    int ii = i & 127;
    int hh = ii >> 5, ci = ii & 31;
    int c  = 64 * hh + 32 + ci;
    int j  = 2 * p + jj;
    float v = bwd ? __expf(trans[j * C + c]) : __expf(trans[c * C + j]);
    sm.Msh[p * MROW + jj * 128 + hh * 32 + ci] = __float2half_rn(v);
  }
  for (int l = tid; l < L; l += THREADS) sm.labs[l] = labels[b * L + l];

  const float* xb = x + (size_t)b * T * C;

  // ---- init p (fp32 + fp16 copies), red, xt, nb
  if (tid < C) {
    int tp = bwd ? (D - 1) : 0;
    float w0 = __expf(xb[(size_t)tp * C + tid]);
    #pragma unroll
    for (int cp = 0; cp < 4; ++cp) {
      sm.p32[0][cp * P32PITCH + tid] = w0;
      sm.p16[0][cp * P16PITCH + tid] = __float2half_rn(w0);
    }
    sm.xt[0][tid] = xb[(size_t)t * C + tid];
    float rv = w0;
    #pragma unroll
    for (int o = 16; o; o >>= 1) rv += __shfl_xor_sync(0xffffffffu, rv, o);
    if (lane == 0) sm.red[w] = rv;
  } else if (lane == 0) {
    sm.red[w] = 0.0f;
  }
  if (tid < LMAX + 2) { sm.nb[0][tid] = NEGV; sm.nb[1][tid] = NEGV; }
  __syncthreads();
  if (tid == 0) {
    if (!bwd) sm.nb[0][1] = xb[sm.labs[0]];
    else      sm.nb[0][L] = 0.0f;
  }

  float xc0 = xb[(size_t)t * C + j0];
  float xc1 = xb[(size_t)t * C + j0 + 1];

  float logS = 0.0f;
  int   cur  = 0;

  const bool isnum = (h == 1);
  const int  lnum  = jp;
  int lab0 = 0, lab1 = -1;
  if (isnum && lnum < L) {
    lab0 = sm.labs[lnum];
    lab1 = (lnum + 1 < L) ? sm.labs[lnum + 1] : -1;
  }

  const uint4* Mh0 = reinterpret_cast<const uint4*>(sm.Msh + jp * MROW + h * 32);
  const uint4* Mh1 = reinterpret_cast<const uint4*>(sm.Msh + jp * MROW + 128 + h * 32);

  for (int k = 0; k < nsteps; ++k) {
    __syncthreads();   // p32/p16[cur], xt[cur], nb[cur], red visible
    const bool more = (k + 1) < nsteps;
    const int  nxt  = cur ^ 1;

    float pf0 = 0.0f, pf1 = 0.0f;
    if (more) {
      float2 xn = *reinterpret_cast<const float2*>(xb + (size_t)(t + dt) * C + j0);
      pf0 = xn.x; pf1 = xn.y;
    }

    // ---- lagged normalizer (previous step's sum)
    float S = sm.red[lane & 15];
    #pragma unroll
    for (int o = 8; o; o >>= 1) S += __shfl_xor_sync(0xffffffffu, S, o);
    float rs = __fdividef(1.0f, S);

    // ---- reg half: fp32 FMA2, c in [cbase, cbase+32)
    const float* pr = sm.p32[cur] + 324 * h;   // copy h base (260h) + c offset (64h)
    unsigned long long acc0 = 0ull, acc1 = 0ull;
    #pragma unroll
    for (int q = 0; q < 8; ++q) {
      ulonglong2 pv = *reinterpret_cast<const ulonglong2*>(pr + 4 * q);
      FMA2(acc0, pv.x, MrA[2 * q]);  FMA2(acc0, pv.y, MrA[2 * q + 1]);
      FMA2(acc1, pv.x, MrB[2 * q]);  FMA2(acc1, pv.y, MrB[2 * q + 1]);
    }

    // ---- smem half: fp16 HFMA2, c in [cbase+32, cbase+64)
    const uint4* ph = reinterpret_cast<const uint4*>(sm.p16[cur] + 328 * h + 32); // copy h (264h) + c (64h+32)
    __half2 hacc0 = __float2half2_rn(0.0f);
    __half2 hacc1 = __float2half2_rn(0.0f);
    #pragma unroll
    for (int q = 0; q < 4; ++q) {
      uint4 pm = ph[q];
      uint4 ma = Mh0[q];
      uint4 mb = Mh1[q];
      const __half2* p2 = reinterpret_cast<const __half2*>(&pm);
      const __half2* a2 = reinterpret_cast<const __half2*>(&ma);
      const __half2* b2 = reinterpret_cast<const __half2*>(&mb);
      #pragma unroll
      for (int e = 0; e < 4; ++e) {
        hacc0 = __hfma2(p2[e], a2[e], hacc0);
        hacc1 = __hfma2(p2[e], b2[e], hacc1);
      }
    }

    float y0l, y0h, y1l, y1h;
    UNPACKF2(y0l, y0h, acc0);
    UNPACKF2(y1l, y1h, acc1);
    float2 ha = __half22float2(hacc0);
    float2 hb = __half22float2(hacc1);
    float y0 = (y0l + y0h) + (ha.x + ha.y);
    float y1 = (y1l + y1h) + (hb.x + hb.y);
    y0 += __shfl_xor_sync(0xffffffffu, y0, 1);
    y0 += __shfl_xor_sync(0xffffffffu, y0, 2);
    y1 += __shfl_xor_sync(0xffffffffu, y1, 1);
    y1 += __shfl_xor_sync(0xffffffffu, y1, 2);

    float wn0, wn1;
    if (!bwd) {
      wn0 = y0 * __expf(xc0) * rs;
      wn1 = y1 * __expf(xc1) * rs;
    } else {
      wn0 = y0 * rs;
      wn1 = y1 * rs;
      if (more) { wn0 *= __expf(pf0); wn1 *= __expf(pf1); }
    }
    *reinterpret_cast<float2*>(&sm.p32[nxt][h * P32PITCH + j0]) = make_float2(wn0, wn1);
    *reinterpret_cast<__half2*>(&sm.p16[nxt][h * P16PITCH + j0]) =
        __float22half2_rn(make_float2(wn0, wn1));

    { // per-step red (h==0 contributes)
      float rv = (h == 0) ? (wn0 + wn1) : 0.0f;
      rv += __shfl_xor_sync(0xffffffffu, rv, 4);
      rv += __shfl_xor_sync(0xffffffffu, rv, 8);
      rv += __shfl_xor_sync(0xffffffffu, rv, 16);
      if (lane == 0) sm.red[w] = rv;
    }

    if (h == 2 && more)
      *reinterpret_cast<float2*>(&sm.xt[nxt][j0]) = make_float2(pf0, pf1);

    if (isnum && lnum < L) {
      int l = lnum;
      float nnew;
      if (!bwd) {
        float e = sm.xt[cur][lab0];
        nnew = lse2_fast(sm.nb[cur][l + 1], sm.nb[cur][l]) + e;
      } else {
        float v0 = sm.nb[cur][l + 1] + sm.xt[cur][lab0];
        float v1 = NEGV;
        if (lab1 >= 0) v1 = sm.nb[cur][l + 2] + sm.xt[cur][lab1];
        nnew = lse2_fast(v0, v1);
      }
      sm.nb[nxt][l + 1] = nnew;
    }

    if (tid == 0) logS += __logf(S);

    xc0 = pf0; xc1 = pf1;
    cur ^= 1;
    t   += dt;
  }
  __syncthreads();

  float Sf = sm.red[lane & 15];
  #pragma unroll
  for (int o = 8; o; o >>= 1) Sf += __shfl_xor_sync(0xffffffffu, Sf, o);

  if (!bwd) {
    if (tid < C)  g_f[b][tid] = sm.p32[cur][tid] / Sf;
    if (tid < L)  g_a[b][tid] = sm.nb[cur][tid + 1];
    if (tid == 0) g_lsf[b] = logS + logf(Sf);
  } else {
    if (tid < C)  g_g[b][tid] = sm.p32[cur][tid] / Sf;
    if (tid < L)  g_bt[b][tid] = sm.nb[cur][tid + 1];
    if (tid == 0) g_lsg[b] = logS + logf(Sf);
  }
}

__global__ void __launch_bounds__(1024, 1)
combine_kernel(const int* __restrict__ durations, int B, int L,
               float* __restrict__ out, int out_size)
{
  __shared__ float sc[MAXB];
  const int lane = threadIdx.x & 31;
  const int w    = threadIdx.x >> 5;

  for (int b = w; b < B; b += 32) {
    float dot = 0.0f;
    for (int c = lane; c < C; c += 32) dot += g_f[b][c] * g_g[b][c];
    #pragma unroll
    for (int o = 16; o; o >>= 1) dot += __shfl_xor_sync(0xffffffffu, dot, o);

    float mx = -INFINITY;
    for (int l = lane; l < L; l += 32) mx = fmaxf(mx, g_a[b][l] + g_bt[b][l]);
    #pragma unroll
    for (int o = 16; o; o >>= 1) mx = fmaxf(mx, __shfl_xor_sync(0xffffffffu, mx, o));

    float s = 0.0f;
    for (int l = lane; l < L; l += 32) s += expf(g_a[b][l] + g_bt[b][l] - mx);
    #pragma unroll
    for (int o = 16; o; o >>= 1) s += __shfl_xor_sync(0xffffffffu, s, o);

    if (lane == 0) {
      float num = mx + logf(s);
      float den = logf(dot) + g_lsf[b] + g_lsg[b];
      sc[b] = num - den;
    }
  }
  __syncthreads();
  if (threadIdx.x == 0) {
    float tot = 0.0f;
    for (int i = 0; i < B; ++i) tot += sc[i];   // fixed order => deterministic
    long long fr = 0;
    for (int i = 0; i < B; ++i) fr += durations[i];
    out[0] = tot;
    if (out_size > 1) out[1] = (float)fr;
    if (out_size > 2) out[2] = (float)fr;
  }
}

extern "C" void kernel_launch(void* const* d_in, const int* in_sizes, int n_in,
                              void* d_out, int out_size)
{
  const float* x      = (const float*)d_in[0];
  const float* trans  = (const float*)d_in[1];
  const int*   labels = (const int*)d_in[2];
  const int*   dur    = (const int*)d_in[3];

  int B = in_sizes[3];
  int L = in_sizes[2] / B;
  int T = in_sizes[0] / (B * C);
  int nwork = 2 * B;
  int grid  = nwork < GRID_PAD ? GRID_PAD : nwork;

  size_t smem = sizeof(SmemLayout);
  cudaFuncSetAttribute(chain_kernel, cudaFuncAttributeMaxDynamicSharedMemorySize, (int)smem);

  chain_kernel<<<grid, THREADS, smem>>>(x, trans, labels, dur, T, L, nwork);
  combine_kernel<<<1, 1024>>>(dur, B, L, (float*)d_out, out_size);
}

// round 9
// speedup vs baseline: 1.3755x; 1.2199x over previous
#include <cuda_runtime.h>
#include <cuda_fp16.h>
#include <math.h>

#define NEGV (-1e30f)

constexpr int C        = 256;
constexpr int LMAX     = 128;
constexpr int THREADS  = 512;   // 16 warps
constexpr int MAXB     = 64;
constexpr int P32PITCH = 260;   // floats per fp32 p copy
constexpr int P16PITCH = 264;   // halves per fp16 p copy
constexpr int MSH_Q    = 4096;  // halves per q-block of Msh0/Msh1 (128 jp * 4 h * 8)
constexpr int GRID_PAD = 148;

__device__ float g_f  [MAXB][C];
__device__ float g_g  [MAXB][C];
__device__ float g_a  [MAXB][LMAX];
__device__ float g_bt [MAXB][LMAX];
__device__ float g_lsf[MAXB];
__device__ float g_lsg[MAXB];
__device__ int   g_bar = 0;     // last-CTA ticket; reset by the combiner every call

struct SmemLayout {
  __half Msh0[4 * MSH_Q];         // fp16 M half, even j: [q][jp][h][8]  (32KB)
  __half Msh1[4 * MSH_Q];         // fp16 M half, odd  j                  (32KB)
  float  p32[2][4 * P32PITCH];    // fp32 p, 4 bank-shifted copies, double-buffered
  __half p16[2][4 * P16PITCH];    // fp16 p, 4 copies, double-buffered
  float  xt[2][C];                // x_t for numerator gather
  float  nb[2][LMAX + 2];         // numerator DP (log domain)
  float  red[16];
  float  sc[MAXB];                // per-batch scores (combine phase)
  int    labs[LMAX];
  int    amLast;
};

#define FMA2(acc,a,b)     asm("fma.rn.f32x2 %0, %1, %2, %0;" : "+l"(acc) : "l"(a), "l"(b))
#define PACKF2(d,lo,hi)   asm("mov.b64 %0, {%1, %2};" : "=l"(d) : "f"(lo), "f"(hi))
#define UNPACKF2(lo,hi,v) asm("mov.b64 {%0, %1}, %2;" : "=f"(lo), "=f"(hi) : "l"(v))

__device__ __forceinline__ float lse2_fast(float a, float b) {
  float mx = fmaxf(a, b);
  float mn = fminf(a, b);
  return mx + __logf(1.0f + __expf(mn - mx));
}

__global__ void __launch_bounds__(THREADS, 1)
chain_kernel(const float* __restrict__ x, const float* __restrict__ trans,
             const int* __restrict__ labels, const int* __restrict__ durations,
             int T, int L, int nwork, int grid, int B,
             float* __restrict__ out, int out_size)
{
  extern __shared__ char smraw[];
  SmemLayout& sm = *reinterpret_cast<SmemLayout*>(smraw);

  const int  tid  = threadIdx.x;
  const int  lane = tid & 31;
  const int  w    = tid >> 5;

  if (blockIdx.x < (unsigned)nwork) {
    const int  b    = blockIdx.x >> 1;
    const bool bwd  = blockIdx.x & 1;

    const int jp = w * 8 + (lane >> 2);   // j-pair 0..127
    const int h  = lane & 3;              // c-quarter
    const int j0 = 2 * jp, j1 = j0 + 1;
    const int cbase = h * 64;             // reg: [cbase,cbase+32), smem: [cbase+32,cbase+64)

    const int D      = durations[b];
    const int m      = D >> 1;
    const int nsteps = bwd ? (D - 1 - m) : m;
    const int dt     = bwd ? -1 : 1;
    int t            = bwd ? (D - 1) : 1;

    // ---- register half of M: fp32, c-paired f32x2 (MrA: j0, MrB: j1)
    unsigned long long MrA[16], MrB[16];
    #pragma unroll
    for (int k = 0; k < 16; ++k) {
      int c0 = cbase + 2 * k, c1 = c0 + 1;
      float a0, a1, b0, b1;
      if (!bwd) {
        a0 = __expf(trans[c0 * C + j0]); a1 = __expf(trans[c1 * C + j0]);
        b0 = __expf(trans[c0 * C + j1]); b1 = __expf(trans[c1 * C + j1]);
      } else {
        a0 = __expf(trans[j0 * C + c0]); a1 = __expf(trans[j0 * C + c1]);
        b0 = __expf(trans[j1 * C + c0]); b1 = __expf(trans[j1 * C + c1]);
      }
      PACKF2(MrA[k], a0, a1);
      PACKF2(MrB[k], b0, b1);
    }

    // ---- SMEM half of M: fp16, q-major, even/odd j split (conflict-free LDS.128)
    for (int idx = tid; idx < 128 * 256; idx += THREADS) {
      int p  = idx >> 8;           // jp
      int i  = idx & 255;
      int jj = i >> 7;             // 0: even j, 1: odd j
      int ii = i & 127;
      int hh = ii >> 5, ci = ii & 31;
      int c  = 64 * hh + 32 + ci;
      int j  = 2 * p + jj;
      float v = bwd ? __expf(trans[j * C + c]) : __expf(trans[c * C + j]);
      int dst = (ci >> 3) * MSH_Q + p * 32 + hh * 8 + (ci & 7);
      if (!jj) sm.Msh0[dst] = __float2half_rn(v);
      else     sm.Msh1[dst] = __float2half_rn(v);
    }
    for (int l = tid; l < L; l += THREADS) sm.labs[l] = labels[b * L + l];

    const float* xb = x + (size_t)b * T * C;

    // ---- init p (fp32 + fp16 copies), red, xt, nb
    if (tid < C) {
      int tp = bwd ? (D - 1) : 0;
      float w0 = __expf(xb[(size_t)tp * C + tid]);
      #pragma unroll
      for (int cp = 0; cp < 4; ++cp) {
        sm.p32[0][cp * P32PITCH + tid] = w0;
        sm.p16[0][cp * P16PITCH + tid] = __float2half_rn(w0);
      }
      sm.xt[0][tid] = xb[(size_t)t * C + tid];
      float rv = w0;
      #pragma unroll
      for (int o = 16; o; o >>= 1) rv += __shfl_xor_sync(0xffffffffu, rv, o);
      if (lane == 0) sm.red[w] = rv;
    } else if (lane == 0) {
      sm.red[w] = 0.0f;
    }
    if (tid < LMAX + 2) { sm.nb[0][tid] = NEGV; sm.nb[1][tid] = NEGV; }
    __syncthreads();
    if (tid == 0) {
      if (!bwd) sm.nb[0][1] = xb[sm.labs[0]];
      else      sm.nb[0][L] = 0.0f;
    }

    float xc0 = xb[(size_t)t * C + j0];
    float xc1 = xb[(size_t)t * C + j0 + 1];

    float logS = 0.0f;
    int   cur  = 0;

    const bool isnum = (h == 1);
    const int  lnum  = jp;
    int lab0 = 0, lab1 = -1;
    if (isnum && lnum < L) {
      lab0 = sm.labs[lnum];
      lab1 = (lnum + 1 < L) ? sm.labs[lnum + 1] : -1;
    }

    const __half* M0base = sm.Msh0 + jp * 32 + h * 8;
    const __half* M1base = sm.Msh1 + jp * 32 + h * 8;

    for (int k = 0; k < nsteps; ++k) {
      __syncthreads();   // p32/p16[cur], xt[cur], nb[cur], red visible
      const bool more = (k + 1) < nsteps;
      const int  nxt  = cur ^ 1;

      float pf0 = 0.0f, pf1 = 0.0f;
      if (more) {
        float2 xn = *reinterpret_cast<const float2*>(xb + (size_t)(t + dt) * C + j0);
        pf0 = xn.x; pf1 = xn.y;
      }

      // ---- lagged normalizer (previous step's sum)
      float S = sm.red[lane & 15];
      #pragma unroll
      for (int o = 8; o; o >>= 1) S += __shfl_xor_sync(0xffffffffu, S, o);
      float rs = __fdividef(1.0f, S);

      // ---- reg half: fp32 FMA2, c in [cbase, cbase+32)
      const float* pr = sm.p32[cur] + 324 * h;
      unsigned long long acc0 = 0ull, acc1 = 0ull;
      #pragma unroll
      for (int q = 0; q < 8; ++q) {
        ulonglong2 pv = *reinterpret_cast<const ulonglong2*>(pr + 4 * q);
        FMA2(acc0, pv.x, MrA[2 * q]);  FMA2(acc0, pv.y, MrA[2 * q + 1]);
        FMA2(acc1, pv.x, MrB[2 * q]);  FMA2(acc1, pv.y, MrB[2 * q + 1]);
      }

      // ---- smem half: fp16 HFMA2, c in [cbase+32, cbase+64)
      const uint4* ph = reinterpret_cast<const uint4*>(sm.p16[cur] + 328 * h + 32);
      __half2 hacc0 = __float2half2_rn(0.0f);
      __half2 hacc1 = __float2half2_rn(0.0f);
      #pragma unroll
      for (int q = 0; q < 4; ++q) {
        uint4 pm = ph[q];
        uint4 ma = *reinterpret_cast<const uint4*>(M0base + q * MSH_Q);
        uint4 mb = *reinterpret_cast<const uint4*>(M1base + q * MSH_Q);
        const __half2* p2 = reinterpret_cast<const __half2*>(&pm);
        const __half2* a2 = reinterpret_cast<const __half2*>(&ma);
        const __half2* b2 = reinterpret_cast<const __half2*>(&mb);
        #pragma unroll
        for (int e = 0; e < 4; ++e) {
          hacc0 = __hfma2(p2[e], a2[e], hacc0);
          hacc1 = __hfma2(p2[e], b2[e], hacc1);
        }
      }

      float y0l, y0h, y1l, y1h;
      UNPACKF2(y0l, y0h, acc0);
      UNPACKF2(y1l, y1h, acc1);
      float2 ha = __half22float2(hacc0);
      float2 hb = __half22float2(hacc1);
      float y0 = (y0l + y0h) + (ha.x + ha.y);
      float y1 = (y1l + y1h) + (hb.x + hb.y);
      y0 += __shfl_xor_sync(0xffffffffu, y0, 1);
      y0 += __shfl_xor_sync(0xffffffffu, y0, 2);
      y1 += __shfl_xor_sync(0xffffffffu, y1, 1);
      y1 += __shfl_xor_sync(0xffffffffu, y1, 2);

      float wn0, wn1;
      if (!bwd) {
        wn0 = y0 * __expf(xc0) * rs;
        wn1 = y1 * __expf(xc1) * rs;
      } else {
        wn0 = y0 * rs;
        wn1 = y1 * rs;
        if (more) { wn0 *= __expf(pf0); wn1 *= __expf(pf1); }
      }
      *reinterpret_cast<float2*>(&sm.p32[nxt][h * P32PITCH + j0]) = make_float2(wn0, wn1);
      *reinterpret_cast<__half2*>(&sm.p16[nxt][h * P16PITCH + j0]) =
          __float22half2_rn(make_float2(wn0, wn1));

      { // per-step red (h==0 contributes)
        float rv = (h == 0) ? (wn0 + wn1) : 0.0f;
        rv += __shfl_xor_sync(0xffffffffu, rv, 4);
        rv += __shfl_xor_sync(0xffffffffu, rv, 8);
        rv += __shfl_xor_sync(0xffffffffu, rv, 16);
        if (lane == 0) sm.red[w] = rv;
      }

      if (h == 2 && more)
        *reinterpret_cast<float2*>(&sm.xt[nxt][j0]) = make_float2(pf0, pf1);

      if (isnum && lnum < L) {
        int l = lnum;
        float nnew;
        if (!bwd) {
          float e = sm.xt[cur][lab0];
          nnew = lse2_fast(sm.nb[cur][l + 1], sm.nb[cur][l]) + e;
        } else {
          float v0 = sm.nb[cur][l + 1] + sm.xt[cur][lab0];
          float v1 = NEGV;
          if (lab1 >= 0) v1 = sm.nb[cur][l + 2] + sm.xt[cur][lab1];
          nnew = lse2_fast(v0, v1);
        }
        sm.nb[nxt][l + 1] = nnew;
      }

      if (tid == 0) logS += __logf(S);

      xc0 = pf0; xc1 = pf1;
      cur ^= 1;
      t   += dt;
    }
    __syncthreads();

    float Sf = sm.red[lane & 15];
    #pragma unroll
    for (int o = 8; o; o >>= 1) Sf += __shfl_xor_sync(0xffffffffu, Sf, o);

    if (!bwd) {
      if (tid < C)  g_f[b][tid] = sm.p32[cur][tid] / Sf;
      if (tid < L)  g_a[b][tid] = sm.nb[cur][tid + 1];
      if (tid == 0) g_lsf[b] = logS + logf(Sf);
    } else {
      if (tid < C)  g_g[b][tid] = sm.p32[cur][tid] / Sf;
      if (tid < L)  g_bt[b][tid] = sm.nb[cur][tid + 1];
      if (tid == 0) g_lsg[b] = logS + logf(Sf);
    }
    __syncthreads();
  }

  // ---- last-CTA-done: the final arriver performs the combine ----
  if (tid == 0) {
    __threadfence();                       // release g_f/g_a/g_lsf...
    int ticket = atomicAdd(&g_bar, 1);
    sm.amLast = (ticket == grid - 1);
  }
  __syncthreads();
  if (!sm.amLast) return;
  __threadfence();                         // acquire others' writes

  // combine (512 threads, warp per batch)
  for (int b2 = w; b2 < B; b2 += 16) {
    float dot = 0.0f;
    for (int c = lane; c < C; c += 32) dot += g_f[b2][c] * g_g[b2][c];
    #pragma unroll
    for (int o = 16; o; o >>= 1) dot += __shfl_xor_sync(0xffffffffu, dot, o);

    float mx = -INFINITY;
    for (int l = lane; l < L; l += 32) mx = fmaxf(mx, g_a[b2][l] + g_bt[b2][l]);
    #pragma unroll
    for (int o = 16; o; o >>= 1) mx = fmaxf(mx, __shfl_xor_sync(0xffffffffu, mx, o));

    float s = 0.0f;
    for (int l = lane; l < L; l += 32) s += expf(g_a[b2][l] + g_bt[b2][l] - mx);
    #pragma unroll
    for (int o = 16; o; o >>= 1) s += __shfl_xor_sync(0xffffffffu, s, o);

    if (lane == 0) {
      float num = mx + logf(s);
      float den = logf(dot) + g_lsf[b2] + g_lsg[b2];
      sm.sc[b2] = num - den;
    }
  }
  __syncthreads();
  if (tid == 0) {
    float tot = 0.0f;
    for (int i = 0; i < B; ++i) tot += sm.sc[i];   // fixed order => deterministic
    long long fr = 0;
    for (int i = 0; i < B; ++i) fr += durations[i];
    out[0] = tot;
    if (out_size > 1) out[1] = (float)fr;
    if (out_size > 2) out[2] = (float)fr;
    g_bar = 0;                                     // reset for next (graph) call
    __threadfence();
  }
}

extern "C" void kernel_launch(void* const* d_in, const int* in_sizes, int n_in,
                              void* d_out, int out_size)
{
  const float* x      = (const float*)d_in[0];
  const float* trans  = (const float*)d_in[1];
  const int*   labels = (const int*)d_in[2];
  const int*   dur    = (const int*)d_in[3];

  int B = in_sizes[3];
  int L = in_sizes[2] / B;
  int T = in_sizes[0] / (B * C);
  int nwork = 2 * B;
  int grid  = nwork < GRID_PAD ? GRID_PAD : nwork;

  size_t smem = sizeof(SmemLayout);
  cudaFuncSetAttribute(chain_kernel, cudaFuncAttributeMaxDynamicSharedMemorySize, (int)smem);

  chain_kernel<<<grid, THREADS, smem>>>(x, trans, labels, dur, T, L,
                                        nwork, grid, B, (float*)d_out, out_size);
}

// round 10
// speedup vs baseline: 1.8138x; 1.3186x over previous
#include <cuda_runtime.h>
#include <cuda_fp16.h>
#include <math.h>

#define NEGV (-1e30f)

constexpr int C        = 256;
constexpr int LMAX     = 128;
constexpr int THREADS  = 512;   // 16 warps
constexpr int MAXB     = 64;
constexpr int P16PITCH = 272;   // halves per fp16 p copy (reads & writes bank-conflict-free)
constexpr int GRID_PAD = 148;

__device__ float g_f  [MAXB][C];
__device__ float g_g  [MAXB][C];
__device__ float g_a  [MAXB][LMAX];
__device__ float g_bt [MAXB][LMAX];
__device__ float g_lsf[MAXB];
__device__ float g_lsg[MAXB];
__device__ int   g_bar = 0;     // last-CTA ticket; reset by the combiner every call

struct SmemLayout {
  __half p16[2][4 * P16PITCH];    // fp16 p, 4 bank-shifted copies, double-buffered (8.7KB)
  float  xt[2][C];                // x_t tiles for numerator gather + exp factors
  float  nb[2][LMAX + 2];         // numerator DP (log domain)
  float  red[16];
  float  sc[MAXB];                // per-batch scores (combine phase)
  int    labs[LMAX];
  int    amLast;
};

__device__ __forceinline__ float lse2_fast(float a, float b) {
  float mx = fmaxf(a, b);
  float mn = fminf(a, b);
  return mx + __logf(1.0f + __expf(mn - mx));
}

__global__ void __launch_bounds__(THREADS, 1)
chain_kernel(const float* __restrict__ x, const float* __restrict__ trans,
             const int* __restrict__ labels, const int* __restrict__ durations,
             int T, int L, int nwork, int grid, int B,
             float* __restrict__ out, int out_size)
{
  extern __shared__ char smraw[];
  SmemLayout& sm = *reinterpret_cast<SmemLayout*>(smraw);

  const int  tid  = threadIdx.x;
  const int  lane = tid & 31;
  const int  w    = tid >> 5;

  if (blockIdx.x < (unsigned)nwork) {
    const int  b    = blockIdx.x >> 1;
    const bool bwd  = blockIdx.x & 1;

    const int jp = w * 8 + (lane >> 2);   // j-pair 0..127
    const int h  = lane & 3;              // c-quarter
    const int j0 = 2 * jp, j1 = j0 + 1;
    const int cbase = h * 64;             // this thread's c range: [cbase, cbase+64)

    const int D      = durations[b];
    const int m      = D >> 1;
    const int nsteps = bwd ? (D - 1 - m) : m;
    const int dt     = bwd ? -1 : 1;
    int t            = bwd ? (D - 1) : 1;

    // ---- ALL of M in fp16 registers: 64 c (c-paired half2) x 2 j
    __half2 mA[32], mB[32];
    #pragma unroll
    for (int k = 0; k < 32; ++k) {
      int c0 = cbase + 2 * k, c1 = c0 + 1;
      float a0, a1, b0, b1;
      if (!bwd) {
        a0 = __expf(trans[c0 * C + j0]); a1 = __expf(trans[c1 * C + j0]);
        b0 = __expf(trans[c0 * C + j1]); b1 = __expf(trans[c1 * C + j1]);
      } else {
        a0 = __expf(trans[j0 * C + c0]); a1 = __expf(trans[j0 * C + c1]);
        b0 = __expf(trans[j1 * C + c0]); b1 = __expf(trans[j1 * C + c1]);
      }
      mA[k] = __floats2half2_rn(a0, a1);
      mB[k] = __floats2half2_rn(b0, b1);
    }
    for (int l = tid; l < L; l += THREADS) sm.labs[l] = labels[b * L + l];

    const float* xb = x + (size_t)b * T * C;

    // ---- init p16 (4 copies), red, xt, nb
    if (tid < C) {
      int tp = bwd ? (D - 1) : 0;
      float w0 = __expf(xb[(size_t)tp * C + tid]);
      #pragma unroll
      for (int cp = 0; cp < 4; ++cp)
        sm.p16[0][cp * P16PITCH + tid] = __float2half_rn(w0);
      sm.xt[0][tid] = xb[(size_t)t * C + tid];
      float rv = w0;
      #pragma unroll
      for (int o = 16; o; o >>= 1) rv += __shfl_xor_sync(0xffffffffu, rv, o);
      if (lane == 0) sm.red[w] = rv;
    } else if (lane == 0) {
      sm.red[w] = 0.0f;
    }
    if (tid < LMAX + 2) { sm.nb[0][tid] = NEGV; sm.nb[1][tid] = NEGV; }
    __syncthreads();
    if (tid == 0) {
      if (!bwd) sm.nb[0][1] = xb[sm.labs[0]];
      else      sm.nb[0][L] = 0.0f;
    }

    float xc0 = xb[(size_t)t * C + j0];
    float xc1 = xb[(size_t)t * C + j0 + 1];

    float logS = 0.0f;
    int   cur  = 0;
    float wn0 = 0.0f, wn1 = 0.0f;

    const bool isnum = (h == 1);
    const int  lnum  = jp;
    int lab0 = 0, lab1 = -1;
    if (isnum && lnum < L) {
      lab0 = sm.labs[lnum];
      lab1 = (lnum + 1 < L) ? sm.labs[lnum + 1] : -1;
    }

    // this thread's p-read base: copy h, c offset 64h -> 336h halves (42*16B lines, aligned)
    const int prdoff = 336 * h;
    const int pwroff = h * P16PITCH + j0;

    for (int k = 0; k < nsteps; ++k) {
      __syncthreads();   // p16[cur], xt[cur], nb[cur], red visible
      const bool more = (k + 1) < nsteps;
      const int  nxt  = cur ^ 1;

      float pf0 = 0.0f, pf1 = 0.0f;
      if (more) {
        float2 xn = *reinterpret_cast<const float2*>(xb + (size_t)(t + dt) * C + j0);
        pf0 = xn.x; pf1 = xn.y;
      }

      // ---- lagged normalizer (previous step's sum)
      float S = sm.red[lane & 15];
      #pragma unroll
      for (int o = 8; o; o >>= 1) S += __shfl_xor_sync(0xffffffffu, S, o);
      float rs = __fdividef(1.0f, S);

      // ---- GEMV quarter: 8 LDS.128 of p16 + 64 register-operand HFMA2
      const uint4* ph = reinterpret_cast<const uint4*>(sm.p16[cur] + prdoff);
      __half2 a0 = __float2half2_rn(0.0f), a1 = a0, b0 = a0, b1 = a0;
      #pragma unroll
      for (int q = 0; q < 8; ++q) {
        uint4 pm = ph[q];
        const __half2* p2 = reinterpret_cast<const __half2*>(&pm);
        a0 = __hfma2(p2[0], mA[4 * q + 0], a0);
        a1 = __hfma2(p2[1], mA[4 * q + 1], a1);
        a0 = __hfma2(p2[2], mA[4 * q + 2], a0);
        a1 = __hfma2(p2[3], mA[4 * q + 3], a1);
        b0 = __hfma2(p2[0], mB[4 * q + 0], b0);
        b1 = __hfma2(p2[1], mB[4 * q + 1], b1);
        b0 = __hfma2(p2[2], mB[4 * q + 2], b0);
        b1 = __hfma2(p2[3], mB[4 * q + 3], b1);
      }
      float2 fa0 = __half22float2(a0), fa1 = __half22float2(a1);
      float2 fb0 = __half22float2(b0), fb1 = __half22float2(b1);
      float y0 = (fa0.x + fa0.y) + (fa1.x + fa1.y);
      float y1 = (fb0.x + fb0.y) + (fb1.x + fb1.y);
      // combine 4 h-quarters (symmetric: every lane ends with the full sum)
      y0 += __shfl_xor_sync(0xffffffffu, y0, 1);
      y0 += __shfl_xor_sync(0xffffffffu, y0, 2);
      y1 += __shfl_xor_sync(0xffffffffu, y1, 1);
      y1 += __shfl_xor_sync(0xffffffffu, y1, 2);

      if (!bwd) {
        wn0 = y0 * __expf(xc0) * rs;
        wn1 = y1 * __expf(xc1) * rs;
      } else {
        wn0 = y0 * rs;
        wn1 = y1 * rs;
        if (more) { wn0 *= __expf(pf0); wn1 *= __expf(pf1); }
      }
      *reinterpret_cast<__half2*>(&sm.p16[nxt][pwroff]) =
          __floats2half2_rn(wn0, wn1);

      { // per-step red (h==0 contributes)
        float rv = (h == 0) ? (wn0 + wn1) : 0.0f;
        rv += __shfl_xor_sync(0xffffffffu, rv, 4);
        rv += __shfl_xor_sync(0xffffffffu, rv, 8);
        rv += __shfl_xor_sync(0xffffffffu, rv, 16);
        if (lane == 0) sm.red[w] = rv;
      }

      if (h == 2 && more)
        *reinterpret_cast<float2*>(&sm.xt[nxt][j0]) = make_float2(pf0, pf1);

      if (isnum && lnum < L) {
        int l = lnum;
        float nnew;
        if (!bwd) {
          float e = sm.xt[cur][lab0];
          nnew = lse2_fast(sm.nb[cur][l + 1], sm.nb[cur][l]) + e;
        } else {
          float v0 = sm.nb[cur][l + 1] + sm.xt[cur][lab0];
          float v1 = NEGV;
          if (lab1 >= 0) v1 = sm.nb[cur][l + 2] + sm.xt[cur][lab1];
          nnew = lse2_fast(v0, v1);
        }
        sm.nb[nxt][l + 1] = nnew;
      }

      if (tid == 0) logS += __logf(S);

      xc0 = pf0; xc1 = pf1;
      cur ^= 1;
      t   += dt;
    }
    __syncthreads();

    float Sf = sm.red[lane & 15];
    #pragma unroll
    for (int o = 8; o; o >>= 1) Sf += __shfl_xor_sync(0xffffffffu, Sf, o);

    if (!bwd) {
      if (h == 0) {   // final w held in registers (identical across h lanes)
        g_f[b][j0] = wn0 / Sf;
        g_f[b][j1] = wn1 / Sf;
      }
      if (tid < L)  g_a[b][tid] = sm.nb[cur][tid + 1];
      if (tid == 0) g_lsf[b] = logS + logf(Sf);
    } else {
      if (h == 0) {
        g_g[b][j0] = wn0 / Sf;
        g_g[b][j1] = wn1 / Sf;
      }
      if (tid < L)  g_bt[b][tid] = sm.nb[cur][tid + 1];
      if (tid == 0) g_lsg[b] = logS + logf(Sf);
    }
    __syncthreads();
  }

  // ---- last-CTA-done: the final arriver performs the combine ----
  if (tid == 0) {
    __threadfence();                       // release g_f/g_a/g_lsf...
    int ticket = atomicAdd(&g_bar, 1);
    sm.amLast = (ticket == grid - 1);
  }
  __syncthreads();
  if (!sm.amLast) return;
  __threadfence();                         // acquire others' writes

  // combine (512 threads, warp per batch)
  for (int b2 = w; b2 < B; b2 += 16) {
    float dot = 0.0f;
    for (int c = lane; c < C; c += 32) dot += g_f[b2][c] * g_g[b2][c];
    #pragma unroll
    for (int o = 16; o; o >>= 1) dot += __shfl_xor_sync(0xffffffffu, dot, o);

    float mx = -INFINITY;
    for (int l = lane; l < L; l += 32) mx = fmaxf(mx, g_a[b2][l] + g_bt[b2][l]);
    #pragma unroll
    for (int o = 16; o; o >>= 1) mx = fmaxf(mx, __shfl_xor_sync(0xffffffffu, mx, o));

    float s = 0.0f;
    for (int l = lane; l < L; l += 32) s += expf(g_a[b2][l] + g_bt[b2][l] - mx);
    #pragma unroll
    for (int o = 16; o; o >>= 1) s += __shfl_xor_sync(0xffffffffu, s, o);

    if (lane == 0) {
      float num = mx + logf(s);
      float den = logf(dot) + g_lsf[b2] + g_lsg[b2];
      sm.sc[b2] = num - den;
    }
  }
  __syncthreads();
  if (tid == 0) {
    float tot = 0.0f;
    for (int i = 0; i < B; ++i) tot += sm.sc[i];   // fixed order => deterministic
    long long fr = 0;
    for (int i = 0; i < B; ++i) fr += durations[i];
    out[0] = tot;
    if (out_size > 1) out[1] = (float)fr;
    if (out_size > 2) out[2] = (float)fr;
    g_bar = 0;                                     // reset for next (graph) call
    __threadfence();
  }
}

extern "C" void kernel_launch(void* const* d_in, const int* in_sizes, int n_in,
                              void* d_out, int out_size)
{
  const float* x      = (const float*)d_in[0];
  const float* trans  = (const float*)d_in[1];
  const int*   labels = (const int*)d_in[2];
  const int*   dur    = (const int*)d_in[3];

  int B = in_sizes[3];
  int L = in_sizes[2] / B;
  int T = in_sizes[0] / (B * C);
  int nwork = 2 * B;
  int grid  = nwork < GRID_PAD ? GRID_PAD : nwork;

  size_t smem = sizeof(SmemLayout);
  cudaFuncSetAttribute(chain_kernel, cudaFuncAttributeMaxDynamicSharedMemorySize, (int)smem);

  chain_kernel<<<grid, THREADS, smem>>>(x, trans, labels, dur, T, L,
                                        nwork, grid, B, (float*)d_out, out_size);
}